// round 2
// baseline (speedup 1.0000x reference)
#include <cuda_runtime.h>
#include <math.h>

#define B_   2
#define L_   2048
#define E_   2048
#define HQ_  16
#define HKV_ 2
#define D_   128
#define G_   (HQ_/HKV_)

#define BM 64
#define BN 64
#define PAD 68   // row stride (floats) for transposed smem tiles; multiple of 4 for LDS.128

// ---------------- scratch (static device globals; no allocation allowed) ----
__device__ float g_q[(size_t)B_*HQ_*L_*D_];     // [B][HQ][L][D]
__device__ float g_k[(size_t)B_*HKV_*L_*D_];    // [B][HKV][L][D]
__device__ float g_v[(size_t)B_*HKV_*L_*D_];    // [B][HKV][L][D]
__device__ float g_ctx[(size_t)B_*L_*HQ_*D_];   // [B*L][HQ*D]

// ============================================================================
// SGEMM: C = A[M,K] @ W[K,N] (+bias)
// MODE 0: row-major C[M,N].  MODE 1: scatter into [B][H][L][D] scratch.
// BM=BN=128, BK=16, 256 threads, 8x8 per thread, double-buffered smem.
// ============================================================================
template<int MODE, int H>
__global__ void __launch_bounds__(256, 2) sgemm_kernel(
    const float* __restrict__ A, const float* __restrict__ W,
    const float* __restrict__ bias, float* __restrict__ C,
    int M, int N, int K)
{
    __shared__ float As[2][16][128];   // transposed A tile: As[k][m]
    __shared__ float Bs[2][16][128];   // Bs[k][n]

    const int tid = threadIdx.x;
    const int tx = tid & 15, ty = tid >> 4;
    const int m0 = blockIdx.y * 128, n0 = blockIdx.x * 128;

    float acc[8][8];
#pragma unroll
    for (int i = 0; i < 8; i++)
#pragma unroll
        for (int j = 0; j < 8; j++) acc[i][j] = 0.f;

    const int NT = K >> 4;

    float4 ra[2], rb[2];

    // --- prologue: load tile 0 ---
#pragma unroll
    for (int u = 0; u < 2; u++) {
        int idx = tid + u * 256;
        int r = idx >> 2, c4 = idx & 3;
        ra[u] = *(const float4*)&A[(size_t)(m0 + r) * K + c4 * 4];
        int rw = idx >> 5, cw = idx & 31;
        rb[u] = *(const float4*)&W[(size_t)rw * N + n0 + cw * 4];
    }
#pragma unroll
    for (int u = 0; u < 2; u++) {
        int idx = tid + u * 256;
        int r = idx >> 2, c4 = idx & 3;
        As[0][c4 * 4 + 0][r] = ra[u].x;
        As[0][c4 * 4 + 1][r] = ra[u].y;
        As[0][c4 * 4 + 2][r] = ra[u].z;
        As[0][c4 * 4 + 3][r] = ra[u].w;
        int rw = idx >> 5, cw = idx & 31;
        *(float4*)&Bs[0][rw][cw * 4] = rb[u];
    }
    __syncthreads();

    for (int kt = 0; kt < NT; kt++) {
        const int buf = kt & 1;
        if (kt + 1 < NT) {
#pragma unroll
            for (int u = 0; u < 2; u++) {
                int idx = tid + u * 256;
                int r = idx >> 2, c4 = idx & 3;
                ra[u] = *(const float4*)&A[(size_t)(m0 + r) * K + (kt + 1) * 16 + c4 * 4];
                int rw = idx >> 5, cw = idx & 31;
                rb[u] = *(const float4*)&W[(size_t)((kt + 1) * 16 + rw) * N + n0 + cw * 4];
            }
        }
#pragma unroll
        for (int kk = 0; kk < 16; kk++) {
            float4 a0 = *(const float4*)&As[buf][kk][ty * 4];
            float4 a1 = *(const float4*)&As[buf][kk][64 + ty * 4];
            float4 b0 = *(const float4*)&Bs[buf][kk][tx * 4];
            float4 b1 = *(const float4*)&Bs[buf][kk][64 + tx * 4];
            float av[8] = {a0.x, a0.y, a0.z, a0.w, a1.x, a1.y, a1.z, a1.w};
            float bv[8] = {b0.x, b0.y, b0.z, b0.w, b1.x, b1.y, b1.z, b1.w};
#pragma unroll
            for (int i = 0; i < 8; i++)
#pragma unroll
                for (int j = 0; j < 8; j++)
                    acc[i][j] = fmaf(av[i], bv[j], acc[i][j]);
        }
        if (kt + 1 < NT) {
            const int nb = buf ^ 1;
#pragma unroll
            for (int u = 0; u < 2; u++) {
                int idx = tid + u * 256;
                int r = idx >> 2, c4 = idx & 3;
                As[nb][c4 * 4 + 0][r] = ra[u].x;
                As[nb][c4 * 4 + 1][r] = ra[u].y;
                As[nb][c4 * 4 + 2][r] = ra[u].z;
                As[nb][c4 * 4 + 3][r] = ra[u].w;
                int rw = idx >> 5, cw = idx & 31;
                *(float4*)&Bs[nb][rw][cw * 4] = rb[u];
            }
        }
        __syncthreads();
    }

    // --- epilogue ---
#pragma unroll
    for (int i = 0; i < 8; i++) {
        int row = m0 + ((i < 4) ? ty * 4 + i : 64 + ty * 4 + i - 4);
#pragma unroll
        for (int jh = 0; jh < 2; jh++) {
            int col = n0 + (jh ? 64 + tx * 4 : tx * 4);
            float4 r;
            r.x = acc[i][jh * 4 + 0];
            r.y = acc[i][jh * 4 + 1];
            r.z = acc[i][jh * 4 + 2];
            r.w = acc[i][jh * 4 + 3];
            if (bias) {
                float4 bb = *(const float4*)&bias[col];
                r.x += bb.x; r.y += bb.y; r.z += bb.z; r.w += bb.w;
            }
            if (MODE == 0) {
                *(float4*)&C[(size_t)row * N + col] = r;
            } else {
                int h = col >> 7, d = col & 127;
                int b = row >> 11, l = row & 2047;
                *(float4*)&C[(((size_t)(b * H + h)) * L_ + l) * D_ + d] = r;
            }
        }
    }
}

// ============================================================================
// RoPE (in-place over [B][H][L][D], half-split convention)
// ============================================================================
__global__ void rope_kernel(float* __restrict__ x, int total)
{
    int idx = blockIdx.x * blockDim.x + threadIdx.x;
    if (idx >= total) return;
    int d  = idx & 63;
    int l  = (idx >> 6) & (L_ - 1);
    int bh = idx >> 17;
    size_t base = ((size_t)bh * L_ + l) * D_;
    float inv = powf(1.0e6f, -(float)d * (1.0f / 64.0f));
    float ang = (float)l * inv;
    float s, c;
    sincosf(ang, &s, &c);
    float x1 = x[base + d], x2 = x[base + d + 64];
    x[base + d]      = x1 * c - x2 * s;
    x[base + d + 64] = x2 * c + x1 * s;
}

// ============================================================================
// Causal flash attention, fp32.  grid = (L/BM, HQ, B), 256 threads.
// Dynamic smem: Qs[128][PAD] | Ks[128][PAD] | Vs[64][128] | Ps[64][PAD]
// ============================================================================
#define FLASH_SMEM ((128 * PAD * 2 + 64 * 128 + 64 * PAD) * (int)sizeof(float))

__global__ void __launch_bounds__(256) flash_kernel(
    const float* __restrict__ q, const float* __restrict__ k,
    const float* __restrict__ v, float* __restrict__ out)
{
    extern __shared__ float sm[];
    float* Qs = sm;                     // [128][PAD] transposed (d-major)
    float* Ks = Qs + 128 * PAD;         // [128][PAD] transposed
    float* Vs = Ks + 128 * PAD;         // [64][128] row-major
    float* Ps = Vs + 64 * 128;          // [64][PAD]

    const int tid = threadIdx.x;
    const int tx = tid & 15, ty = tid >> 4;
    const int qt = blockIdx.x, h = blockIdx.y, b = blockIdx.z;
    const int hk = h / G_;
    const float scale = 0.08838834764831845f;  // 1/sqrt(128)

    const float* qp = q + (((size_t)b * HQ_ + h) * L_ + (size_t)qt * BM) * D_;
    const float* kp = k + ((size_t)b * HKV_ + hk) * L_ * D_;
    const float* vp = v + ((size_t)b * HKV_ + hk) * L_ * D_;

    // load Q tile transposed
#pragma unroll
    for (int u = 0; u < 8; u++) {
        int f4 = tid + u * 256;
        int r = f4 >> 5, c4 = f4 & 31;
        float4 val = *(const float4*)&qp[(size_t)r * 128 + c4 * 4];
        Qs[(c4 * 4 + 0) * PAD + r] = val.x;
        Qs[(c4 * 4 + 1) * PAD + r] = val.y;
        Qs[(c4 * 4 + 2) * PAD + r] = val.z;
        Qs[(c4 * 4 + 3) * PAD + r] = val.w;
    }

    float m[4], lsum[4], o[4][8];
#pragma unroll
    for (int i = 0; i < 4; i++) {
        m[i] = -1e30f; lsum[i] = 0.f;
#pragma unroll
        for (int j = 0; j < 8; j++) o[i][j] = 0.f;
    }

    for (int kt = 0; kt <= qt; kt++) {
        const float* kpt = kp + (size_t)kt * BN * D_;
        const float* vpt = vp + (size_t)kt * BN * D_;
#pragma unroll
        for (int u = 0; u < 8; u++) {
            int f4 = tid + u * 256;
            int r = f4 >> 5, c4 = f4 & 31;
            float4 kv4 = *(const float4*)&kpt[(size_t)r * 128 + c4 * 4];
            Ks[(c4 * 4 + 0) * PAD + r] = kv4.x;
            Ks[(c4 * 4 + 1) * PAD + r] = kv4.y;
            Ks[(c4 * 4 + 2) * PAD + r] = kv4.z;
            Ks[(c4 * 4 + 3) * PAD + r] = kv4.w;
            float4 vv4 = *(const float4*)&vpt[(size_t)r * 128 + c4 * 4];
            *(float4*)&Vs[r * 128 + c4 * 4] = vv4;
        }
        __syncthreads();

        // ---- S = Q K^T (fragment 4x4 per thread) ----
        float s[4][4];
#pragma unroll
        for (int i = 0; i < 4; i++)
#pragma unroll
            for (int j = 0; j < 4; j++) s[i][j] = 0.f;

#pragma unroll 4
        for (int kk = 0; kk < 128; kk++) {
            float4 qv = *(const float4*)&Qs[kk * PAD + ty * 4];
            float4 kv = *(const float4*)&Ks[kk * PAD + tx * 4];
            float qa[4] = {qv.x, qv.y, qv.z, qv.w};
            float ka[4] = {kv.x, kv.y, kv.z, kv.w};
#pragma unroll
            for (int i = 0; i < 4; i++)
#pragma unroll
                for (int j = 0; j < 4; j++)
                    s[i][j] = fmaf(qa[i], ka[j], s[i][j]);
        }

        // scale + causal mask (only diagonal tile needs it)
#pragma unroll
        for (int i = 0; i < 4; i++)
#pragma unroll
            for (int j = 0; j < 4; j++) {
                s[i][j] *= scale;
                if (kt == qt && (tx * 4 + j) > (ty * 4 + i)) s[i][j] = -1e30f;
            }

        // ---- online softmax ----
#pragma unroll
        for (int i = 0; i < 4; i++) {
            float rm = fmaxf(fmaxf(s[i][0], s[i][1]), fmaxf(s[i][2], s[i][3]));
#pragma unroll
            for (int off = 8; off >= 1; off >>= 1)
                rm = fmaxf(rm, __shfl_xor_sync(0xffffffffu, rm, off, 16));
            float mn = fmaxf(m[i], rm);
            float alpha = __expf(m[i] - mn);
            float p0 = __expf(s[i][0] - mn);
            float p1 = __expf(s[i][1] - mn);
            float p2 = __expf(s[i][2] - mn);
            float p3 = __expf(s[i][3] - mn);
            float rs = p0 + p1 + p2 + p3;
#pragma unroll
            for (int off = 8; off >= 1; off >>= 1)
                rs += __shfl_xor_sync(0xffffffffu, rs, off, 16);
            lsum[i] = lsum[i] * alpha + rs;
            m[i] = mn;
#pragma unroll
            for (int j = 0; j < 8; j++) o[i][j] *= alpha;
            Ps[(ty * 4 + i) * PAD + tx * 4 + 0] = p0;
            Ps[(ty * 4 + i) * PAD + tx * 4 + 1] = p1;
            Ps[(ty * 4 + i) * PAD + tx * 4 + 2] = p2;
            Ps[(ty * 4 + i) * PAD + tx * 4 + 3] = p3;
        }
        __syncthreads();

        // ---- O += P @ V ----
#pragma unroll 2
        for (int c = 0; c < BN; c++) {
            float4 v0 = *(const float4*)&Vs[c * 128 + tx * 4];
            float4 v1 = *(const float4*)&Vs[c * 128 + 64 + tx * 4];
#pragma unroll
            for (int i = 0; i < 4; i++) {
                float pi = Ps[(ty * 4 + i) * PAD + c];
                o[i][0] = fmaf(pi, v0.x, o[i][0]);
                o[i][1] = fmaf(pi, v0.y, o[i][1]);
                o[i][2] = fmaf(pi, v0.z, o[i][2]);
                o[i][3] = fmaf(pi, v0.w, o[i][3]);
                o[i][4] = fmaf(pi, v1.x, o[i][4]);
                o[i][5] = fmaf(pi, v1.y, o[i][5]);
                o[i][6] = fmaf(pi, v1.z, o[i][6]);
                o[i][7] = fmaf(pi, v1.w, o[i][7]);
            }
        }
        __syncthreads();
    }

    // ---- epilogue: out [B][L][HQ*D] ----
#pragma unroll
    for (int i = 0; i < 4; i++) {
        float inv = 1.0f / lsum[i];
        int qrow = qt * BM + ty * 4 + i;
        float* op = out + ((size_t)b * L_ + qrow) * (HQ_ * D_) + h * D_;
        float4 r0, r1;
        r0.x = o[i][0] * inv; r0.y = o[i][1] * inv;
        r0.z = o[i][2] * inv; r0.w = o[i][3] * inv;
        r1.x = o[i][4] * inv; r1.y = o[i][5] * inv;
        r1.z = o[i][6] * inv; r1.w = o[i][7] * inv;
        *(float4*)&op[tx * 4]      = r0;
        *(float4*)&op[64 + tx * 4] = r1;
    }
}

// ============================================================================
// launch
// ============================================================================
extern "C" void kernel_launch(void* const* d_in, const int* in_sizes, int n_in,
                              void* d_out, int out_size)
{
    (void)in_sizes; (void)n_in; (void)out_size;
    const float* hs = (const float*)d_in[0];
    const float* Wq = (const float*)d_in[1];
    const float* bq = (const float*)d_in[2];
    const float* Wk = (const float*)d_in[3];
    const float* bk = (const float*)d_in[4];
    const float* Wv = (const float*)d_in[5];
    const float* bv = (const float*)d_in[6];
    const float* Wo = (const float*)d_in[7];
    float* out = (float*)d_out;

    float *qg, *kg, *vg, *ctx;
    cudaGetSymbolAddress((void**)&qg,  g_q);
    cudaGetSymbolAddress((void**)&kg,  g_k);
    cudaGetSymbolAddress((void**)&vg,  g_v);
    cudaGetSymbolAddress((void**)&ctx, g_ctx);

    cudaFuncSetAttribute(flash_kernel,
                         cudaFuncAttributeMaxDynamicSharedMemorySize, FLASH_SMEM);

    const int M = B_ * L_;

    // QKV projections (+bias, scatter to [B][H][L][D])
    sgemm_kernel<1, HQ_ ><<<dim3((HQ_ * D_) / 128, M / 128), 256>>>(hs, Wq, bq, qg, M, HQ_ * D_, E_);
    sgemm_kernel<1, HKV_><<<dim3((HKV_ * D_) / 128, M / 128), 256>>>(hs, Wk, bk, kg, M, HKV_ * D_, E_);
    sgemm_kernel<1, HKV_><<<dim3((HKV_ * D_) / 128, M / 128), 256>>>(hs, Wv, bv, vg, M, HKV_ * D_, E_);

    // RoPE on q and k
    const int tq = B_ * HQ_ * L_ * 64;
    const int tk = B_ * HKV_ * L_ * 64;
    rope_kernel<<<(tq + 255) / 256, 256>>>(qg, tq);
    rope_kernel<<<(tk + 255) / 256, 256>>>(kg, tk);

    // causal flash attention -> ctx [B*L][HQ*D]
    flash_kernel<<<dim3(L_ / BM, HQ_, B_), 256, FLASH_SMEM>>>(qg, kg, vg, ctx);

    // output projection -> d_out [B*L][E]
    sgemm_kernel<0, 1><<<dim3(E_ / 128, M / 128), 256>>>(ctx, Wo, nullptr, out, M, E_, E_);
}

// round 10
// speedup vs baseline: 1.3637x; 1.3637x over previous
#include <cuda_runtime.h>
#include <math.h>
#include <stdint.h>

#define B_   2
#define L_   2048
#define E_   2048
#define HQ_  16
#define HKV_ 2
#define D_   128
#define G_   (HQ_/HKV_)
#define M_   (B_*L_)

#define BM 64
#define BN 64
#define PAD 68

// ---------------- scratch (static device globals) ---------------------------
__device__ float g_q[(size_t)B_*HQ_*L_*D_];
__device__ float g_k[(size_t)B_*HKV_*L_*D_];
__device__ float g_v[(size_t)B_*HKV_*L_*D_];
__device__ float g_ctx[(size_t)B_*L_*HQ_*D_];
__device__ float g_wtq[(size_t)E_*HQ_*D_];    // Wq^T  [N][K]
__device__ float g_wtk[(size_t)E_*HKV_*D_];   // Wk^T
__device__ float g_wtv[(size_t)E_*HKV_*D_];   // Wv^T
__device__ float g_wto[(size_t)E_*E_];        // Wo^T

// ============================================================================
// helpers
// ============================================================================
__device__ __forceinline__ uint32_t f2tf32(float f) {
    uint32_t u;
    asm("cvt.rna.tf32.f32 %0, %1;" : "=r"(u) : "f"(f));
    return u;
}
__device__ __forceinline__ void mma_tf32(float* d, const float4& a, const float2& b) {
    asm volatile(
        "mma.sync.aligned.m16n8k8.row.col.f32.tf32.tf32.f32 "
        "{%0,%1,%2,%3}, {%4,%5,%6,%7}, {%8,%9}, {%0,%1,%2,%3};"
        : "+f"(d[0]), "+f"(d[1]), "+f"(d[2]), "+f"(d[3])
        : "r"(__float_as_uint(a.x)), "r"(__float_as_uint(a.y)),
          "r"(__float_as_uint(a.z)), "r"(__float_as_uint(a.w)),
          "r"(__float_as_uint(b.x)), "r"(__float_as_uint(b.y)));
}

// ============================================================================
// weight transpose: in[R][C] -> out[C][R]
// ============================================================================
__global__ void transpose_kernel(const float* __restrict__ in, float* __restrict__ out,
                                 int R, int C)
{
    __shared__ float t[32][33];
    int c0 = blockIdx.x * 32, r0 = blockIdx.y * 32;
    int x = threadIdx.x, y = threadIdx.y;
#pragma unroll
    for (int i = 0; i < 32; i += 8)
        t[y + i][x] = in[(size_t)(r0 + y + i) * C + c0 + x];
    __syncthreads();
#pragma unroll
    for (int i = 0; i < 32; i += 8)
        out[(size_t)(c0 + y + i) * R + r0 + x] = t[x][y + i];
}

// ============================================================================
// tf32 mma.sync GEMM: C[M,N] = A[M,K] @ Bt[N,K]^T (+bias)
// CTA tile 128x128, warp grid 2(M)x4(N), warp tile 64x32, KC=32, dbl-buffered.
// Smem holds tiles pre-permuted into m16n8k8 fragment order:
//   A: [mt(8)][ks(4)][lane(32)][reg(4)]  (float4/lane per (mt,ks))
//   B: [nt(16)][ks(4)][lane(32)][reg(2)] (float2/lane per (nt,ks))
// MODE 0: row-major out.  MODE 1: scatter into [B][H][L][D].
// ============================================================================
#define KC 32
#define A_FLOATS 4096   // 8*4*32*4
#define B_FLOATS 4096   // 16*4*32*2
#define GEMM_SMEM ((2*A_FLOATS + 2*B_FLOATS) * (int)sizeof(float))

__device__ __forceinline__ void load_tileA(float* __restrict__ dst,
                                           const float* __restrict__ src,
                                           int row0, int ld, int k0, int tid)
{
#pragma unroll
    for (int u = 0; u < 4; u++) {
        int idx = tid + u * 256;
        int r = idx >> 3, c4 = idx & 7;
        float4 v = *(const float4*)(src + (size_t)(row0 + r) * ld + k0 + c4 * 4);
        uint32_t w[4] = {f2tf32(v.x), f2tf32(v.y), f2tf32(v.z), f2tf32(v.w)};
        int mt = r >> 4, r16 = r & 15;
        int lanebase = (r16 & 7) * 4;
        int regbase  = (r16 >> 3);
#pragma unroll
        for (int e = 0; e < 4; e++) {
            int k = c4 * 4 + e;
            int ks = k >> 3, kc = k & 7;
            int lane = lanebase + (kc & 3);
            int reg  = ((kc >> 2) << 1) + regbase;
            dst[(((mt << 2) + ks) << 7) + (lane << 2) + reg] = __uint_as_float(w[e]);
        }
    }
}

__device__ __forceinline__ void load_tileB(float* __restrict__ dst,
                                           const float* __restrict__ src,
                                           int n0, int ld, int k0, int tid)
{
#pragma unroll
    for (int u = 0; u < 4; u++) {
        int idx = tid + u * 256;
        int r = idx >> 3, c4 = idx & 7;   // r = n row of Bt
        float4 v = *(const float4*)(src + (size_t)(n0 + r) * ld + k0 + c4 * 4);
        uint32_t w[4] = {f2tf32(v.x), f2tf32(v.y), f2tf32(v.z), f2tf32(v.w)};
        int nt = r >> 3, n8 = r & 7;
        int lanebase = n8 * 4;
#pragma unroll
        for (int e = 0; e < 4; e++) {
            int k = c4 * 4 + e;
            int ks = k >> 3, kc = k & 7;
            int lane = lanebase + (kc & 3);
            int reg  = kc >> 2;
            dst[(((nt << 2) + ks) << 6) + (lane << 1) + reg] = __uint_as_float(w[e]);
        }
    }
}

template<int MODE, int H>
__global__ void __launch_bounds__(256, 2)
mma_gemm(const float* __restrict__ A, const float* __restrict__ Bt,
         const float* __restrict__ bias, float* __restrict__ C,
         int N, int K)
{
    extern __shared__ float sm[];
    float* As = sm;                    // [2][A_FLOATS]
    float* Bs = sm + 2 * A_FLOATS;     // [2][B_FLOATS]

    const int tid  = threadIdx.x;
    const int wid  = tid >> 5;
    const int lane = tid & 31;
    const int mw   = wid & 1;          // 0/1 -> M half
    const int nw   = wid >> 1;         // 0..3 -> N quarter
    const int m0 = blockIdx.y * 128, n0 = blockIdx.x * 128;

    float acc[4][4][4];
#pragma unroll
    for (int i = 0; i < 4; i++)
#pragma unroll
        for (int j = 0; j < 4; j++)
#pragma unroll
            for (int e = 0; e < 4; e++) acc[i][j][e] = 0.f;

    // prologue: chunk 0 -> buf 0
    load_tileA(As, A,  m0, K, 0, tid);
    load_tileB(Bs, Bt, n0, K, 0, tid);
    __syncthreads();

    const int NT = K / KC;
    for (int kt = 0; kt < NT; kt++) {
        const int buf = kt & 1;
        if (kt + 1 < NT) {
            load_tileA(As + (buf ^ 1) * A_FLOATS, A,  m0, K, (kt + 1) * KC, tid);
            load_tileB(Bs + (buf ^ 1) * B_FLOATS, Bt, n0, K, (kt + 1) * KC, tid);
        }
        const float* ab = As + buf * A_FLOATS;
        const float* bb = Bs + buf * B_FLOATS;
#pragma unroll
        for (int ks = 0; ks < 4; ks++) {
            float4 af[4];
            float2 bf[4];
#pragma unroll
            for (int i = 0; i < 4; i++)
                af[i] = *(const float4*)&ab[((((mw * 4 + i) << 2) + ks) << 7) + (lane << 2)];
#pragma unroll
            for (int j = 0; j < 4; j++)
                bf[j] = *(const float2*)&bb[((((nw * 4 + j) << 2) + ks) << 6) + (lane << 1)];
#pragma unroll
            for (int i = 0; i < 4; i++)
#pragma unroll
                for (int j = 0; j < 4; j++)
                    mma_tf32(acc[i][j], af[i], bf[j]);
        }
        __syncthreads();
    }

    // epilogue: c0,c1 at (row, col), c2,c3 at (row+8, col); col = even
    const int rbase = m0 + mw * 64 + (lane >> 2);
    const int cbase = n0 + nw * 32 + (lane & 3) * 2;
#pragma unroll
    for (int i = 0; i < 4; i++) {
#pragma unroll
        for (int j = 0; j < 4; j++) {
            int col = cbase + j * 8;
            float2 lo, hi;
            lo.x = acc[i][j][0]; lo.y = acc[i][j][1];
            hi.x = acc[i][j][2]; hi.y = acc[i][j][3];
            if (bias) {
                float bx = bias[col], by = bias[col + 1];
                lo.x += bx; lo.y += by;
                hi.x += bx; hi.y += by;
            }
            int row = rbase + i * 16;
            if (MODE == 0) {
                *(float2*)&C[(size_t)row * N + col]       = lo;
                *(float2*)&C[(size_t)(row + 8) * N + col] = hi;
            } else {
                int h = col >> 7, d = col & 127;
                int b  = row >> 11, l  = row & 2047;
                int b2 = (row + 8) >> 11, l2 = (row + 8) & 2047;
                *(float2*)&C[(((size_t)(b  * H + h)) * L_ + l ) * D_ + d] = lo;
                *(float2*)&C[(((size_t)(b2 * H + h)) * L_ + l2) * D_ + d] = hi;
            }
        }
    }
}

// ============================================================================
// RoPE (unchanged)
// ============================================================================
__global__ void rope_kernel(float* __restrict__ x, int total)
{
    int idx = blockIdx.x * blockDim.x + threadIdx.x;
    if (idx >= total) return;
    int d  = idx & 63;
    int l  = (idx >> 6) & (L_ - 1);
    int bh = idx >> 17;
    size_t base = ((size_t)bh * L_ + l) * D_;
    float inv = powf(1.0e6f, -(float)d * (1.0f / 64.0f));
    float ang = (float)l * inv;
    float s, c;
    sincosf(ang, &s, &c);
    float x1 = x[base + d], x2 = x[base + d + 64];
    x[base + d]      = x1 * c - x2 * s;
    x[base + d + 64] = x2 * c + x1 * s;
}

// ============================================================================
// Causal flash attention, fp32 (unchanged from passing round)
// ============================================================================
#define FLASH_SMEM ((128 * PAD * 2 + 64 * 128 + 64 * PAD) * (int)sizeof(float))

__global__ void __launch_bounds__(256) flash_kernel(
    const float* __restrict__ q, const float* __restrict__ k,
    const float* __restrict__ v, float* __restrict__ out)
{
    extern __shared__ float sm[];
    float* Qs = sm;
    float* Ks = Qs + 128 * PAD;
    float* Vs = Ks + 128 * PAD;
    float* Ps = Vs + 64 * 128;

    const int tid = threadIdx.x;
    const int tx = tid & 15, ty = tid >> 4;
    const int qt = blockIdx.x, h = blockIdx.y, b = blockIdx.z;
    const int hk = h / G_;
    const float scale = 0.08838834764831845f;

    const float* qp = q + (((size_t)b * HQ_ + h) * L_ + (size_t)qt * BM) * D_;
    const float* kp = k + ((size_t)b * HKV_ + hk) * L_ * D_;
    const float* vp = v + ((size_t)b * HKV_ + hk) * L_ * D_;

#pragma unroll
    for (int u = 0; u < 8; u++) {
        int f4 = tid + u * 256;
        int r = f4 >> 5, c4 = f4 & 31;
        float4 val = *(const float4*)&qp[(size_t)r * 128 + c4 * 4];
        Qs[(c4 * 4 + 0) * PAD + r] = val.x;
        Qs[(c4 * 4 + 1) * PAD + r] = val.y;
        Qs[(c4 * 4 + 2) * PAD + r] = val.z;
        Qs[(c4 * 4 + 3) * PAD + r] = val.w;
    }

    float m[4], lsum[4], o[4][8];
#pragma unroll
    for (int i = 0; i < 4; i++) {
        m[i] = -1e30f; lsum[i] = 0.f;
#pragma unroll
        for (int j = 0; j < 8; j++) o[i][j] = 0.f;
    }

    for (int kt = 0; kt <= qt; kt++) {
        const float* kpt = kp + (size_t)kt * BN * D_;
        const float* vpt = vp + (size_t)kt * BN * D_;
#pragma unroll
        for (int u = 0; u < 8; u++) {
            int f4 = tid + u * 256;
            int r = f4 >> 5, c4 = f4 & 31;
            float4 kv4 = *(const float4*)&kpt[(size_t)r * 128 + c4 * 4];
            Ks[(c4 * 4 + 0) * PAD + r] = kv4.x;
            Ks[(c4 * 4 + 1) * PAD + r] = kv4.y;
            Ks[(c4 * 4 + 2) * PAD + r] = kv4.z;
            Ks[(c4 * 4 + 3) * PAD + r] = kv4.w;
            float4 vv4 = *(const float4*)&vpt[(size_t)r * 128 + c4 * 4];
            *(float4*)&Vs[r * 128 + c4 * 4] = vv4;
        }
        __syncthreads();

        float s[4][4];
#pragma unroll
        for (int i = 0; i < 4; i++)
#pragma unroll
            for (int j = 0; j < 4; j++) s[i][j] = 0.f;

#pragma unroll 4
        for (int kk = 0; kk < 128; kk++) {
            float4 qv = *(const float4*)&Qs[kk * PAD + ty * 4];
            float4 kv = *(const float4*)&Ks[kk * PAD + tx * 4];
            float qa[4] = {qv.x, qv.y, qv.z, qv.w};
            float ka[4] = {kv.x, kv.y, kv.z, kv.w};
#pragma unroll
            for (int i = 0; i < 4; i++)
#pragma unroll
                for (int j = 0; j < 4; j++)
                    s[i][j] = fmaf(qa[i], ka[j], s[i][j]);
        }

#pragma unroll
        for (int i = 0; i < 4; i++)
#pragma unroll
            for (int j = 0; j < 4; j++) {
                s[i][j] *= scale;
                if (kt == qt && (tx * 4 + j) > (ty * 4 + i)) s[i][j] = -1e30f;
            }

#pragma unroll
        for (int i = 0; i < 4; i++) {
            float rm = fmaxf(fmaxf(s[i][0], s[i][1]), fmaxf(s[i][2], s[i][3]));
#pragma unroll
            for (int off = 8; off >= 1; off >>= 1)
                rm = fmaxf(rm, __shfl_xor_sync(0xffffffffu, rm, off, 16));
            float mn = fmaxf(m[i], rm);
            float alpha = __expf(m[i] - mn);
            float p0 = __expf(s[i][0] - mn);
            float p1 = __expf(s[i][1] - mn);
            float p2 = __expf(s[i][2] - mn);
            float p3 = __expf(s[i][3] - mn);
            float rs = p0 + p1 + p2 + p3;
#pragma unroll
            for (int off = 8; off >= 1; off >>= 1)
                rs += __shfl_xor_sync(0xffffffffu, rs, off, 16);
            lsum[i] = lsum[i] * alpha + rs;
            m[i] = mn;
#pragma unroll
            for (int j = 0; j < 8; j++) o[i][j] *= alpha;
            Ps[(ty * 4 + i) * PAD + tx * 4 + 0] = p0;
            Ps[(ty * 4 + i) * PAD + tx * 4 + 1] = p1;
            Ps[(ty * 4 + i) * PAD + tx * 4 + 2] = p2;
            Ps[(ty * 4 + i) * PAD + tx * 4 + 3] = p3;
        }
        __syncthreads();

#pragma unroll 2
        for (int c = 0; c < BN; c++) {
            float4 v0 = *(const float4*)&Vs[c * 128 + tx * 4];
            float4 v1 = *(const float4*)&Vs[c * 128 + 64 + tx * 4];
#pragma unroll
            for (int i = 0; i < 4; i++) {
                float pi = Ps[(ty * 4 + i) * PAD + c];
                o[i][0] = fmaf(pi, v0.x, o[i][0]);
                o[i][1] = fmaf(pi, v0.y, o[i][1]);
                o[i][2] = fmaf(pi, v0.z, o[i][2]);
                o[i][3] = fmaf(pi, v0.w, o[i][3]);
                o[i][4] = fmaf(pi, v1.x, o[i][4]);
                o[i][5] = fmaf(pi, v1.y, o[i][5]);
                o[i][6] = fmaf(pi, v1.z, o[i][6]);
                o[i][7] = fmaf(pi, v1.w, o[i][7]);
            }
        }
        __syncthreads();
    }

#pragma unroll
    for (int i = 0; i < 4; i++) {
        float inv = 1.0f / lsum[i];
        int qrow = qt * BM + ty * 4 + i;
        float* op = out + ((size_t)b * L_ + qrow) * (HQ_ * D_) + h * D_;
        float4 r0, r1;
        r0.x = o[i][0] * inv; r0.y = o[i][1] * inv;
        r0.z = o[i][2] * inv; r0.w = o[i][3] * inv;
        r1.x = o[i][4] * inv; r1.y = o[i][5] * inv;
        r1.z = o[i][6] * inv; r1.w = o[i][7] * inv;
        *(float4*)&op[tx * 4]      = r0;
        *(float4*)&op[64 + tx * 4] = r1;
    }
}

// ============================================================================
// launch
// ============================================================================
extern "C" void kernel_launch(void* const* d_in, const int* in_sizes, int n_in,
                              void* d_out, int out_size)
{
    (void)in_sizes; (void)n_in; (void)out_size;
    const float* hs = (const float*)d_in[0];
    const float* Wq = (const float*)d_in[1];
    const float* bq = (const float*)d_in[2];
    const float* Wk = (const float*)d_in[3];
    const float* bk = (const float*)d_in[4];
    const float* Wv = (const float*)d_in[5];
    const float* bv = (const float*)d_in[6];
    const float* Wo = (const float*)d_in[7];
    float* out = (float*)d_out;

    float *qg, *kg, *vg, *ctx, *wtq, *wtk, *wtv, *wto;
    cudaGetSymbolAddress((void**)&qg,  g_q);
    cudaGetSymbolAddress((void**)&kg,  g_k);
    cudaGetSymbolAddress((void**)&vg,  g_v);
    cudaGetSymbolAddress((void**)&ctx, g_ctx);
    cudaGetSymbolAddress((void**)&wtq, g_wtq);
    cudaGetSymbolAddress((void**)&wtk, g_wtk);
    cudaGetSymbolAddress((void**)&wtv, g_wtv);
    cudaGetSymbolAddress((void**)&wto, g_wto);

    cudaFuncSetAttribute(flash_kernel,
                         cudaFuncAttributeMaxDynamicSharedMemorySize, FLASH_SMEM);
    cudaFuncSetAttribute(mma_gemm<0, 1>,
                         cudaFuncAttributeMaxDynamicSharedMemorySize, GEMM_SMEM);
    cudaFuncSetAttribute(mma_gemm<1, HQ_>,
                         cudaFuncAttributeMaxDynamicSharedMemorySize, GEMM_SMEM);
    cudaFuncSetAttribute(mma_gemm<1, HKV_>,
                         cudaFuncAttributeMaxDynamicSharedMemorySize, GEMM_SMEM);

    dim3 tb(32, 8);
    // weight transposes: W[K][N] -> Wt[N][K]
    transpose_kernel<<<dim3((HQ_*D_)/32,  E_/32), tb>>>(Wq, wtq, E_, HQ_*D_);
    transpose_kernel<<<dim3((HKV_*D_)/32, E_/32), tb>>>(Wk, wtk, E_, HKV_*D_);
    transpose_kernel<<<dim3((HKV_*D_)/32, E_/32), tb>>>(Wv, wtv, E_, HKV_*D_);
    transpose_kernel<<<dim3(E_/32,        E_/32), tb>>>(Wo, wto, E_, E_);

    // projections (tf32 mma.sync)
    mma_gemm<1, HQ_ ><<<dim3((HQ_*D_)/128,  M_/128), 256, GEMM_SMEM>>>(hs, wtq, bq, qg, HQ_*D_,  E_);
    mma_gemm<1, HKV_><<<dim3((HKV_*D_)/128, M_/128), 256, GEMM_SMEM>>>(hs, wtk, bk, kg, HKV_*D_, E_);
    mma_gemm<1, HKV_><<<dim3((HKV_*D_)/128, M_/128), 256, GEMM_SMEM>>>(hs, wtv, bv, vg, HKV_*D_, E_);

    // RoPE
    const int tq = B_ * HQ_ * L_ * 64;
    const int tk = B_ * HKV_ * L_ * 64;
    rope_kernel<<<(tq + 255) / 256, 256>>>(qg, tq);
    rope_kernel<<<(tk + 255) / 256, 256>>>(kg, tk);

    // attention (fp32 flash)
    flash_kernel<<<dim3(L_ / BM, HQ_, B_), 256, FLASH_SMEM>>>(qg, kg, vg, ctx);

    // output projection
    mma_gemm<0, 1><<<dim3(E_/128, M_/128), 256, GEMM_SMEM>>>(ctx, wto, nullptr, out, E_, E_);
}

// round 11
// speedup vs baseline: 1.3648x; 1.0008x over previous
#include <cuda_runtime.h>
#include <math.h>
#include <stdint.h>

#define B_   2
#define L_   2048
#define E_   2048
#define HQ_  16
#define HKV_ 2
#define D_   128
#define G_   (HQ_/HKV_)
#define M_   (B_*L_)

#define BM 64
#define BN 64
#define PAD 68

// ---------------- scratch (static device globals) ---------------------------
__device__ float g_q[(size_t)B_*HQ_*L_*D_];
__device__ float g_k[(size_t)B_*HKV_*L_*D_];
__device__ float g_v[(size_t)B_*HKV_*L_*D_];
__device__ float g_ctx[(size_t)B_*L_*HQ_*D_];
__device__ float g_wtq[(size_t)E_*HQ_*D_];    // Wq^T  [N][K]
__device__ float g_wtk[(size_t)E_*HKV_*D_];   // Wk^T
__device__ float g_wtv[(size_t)E_*HKV_*D_];   // Wv^T
__device__ float g_wto[(size_t)E_*E_];        // Wo^T

// ============================================================================
// helpers
// ============================================================================
__device__ __forceinline__ uint32_t f2tf32(float f) {
    uint32_t u;
    asm("cvt.rna.tf32.f32 %0, %1;" : "=r"(u) : "f"(f));
    return u;
}
__device__ __forceinline__ void mma_tf32(float* d, const float4& a, const float2& b) {
    asm volatile(
        "mma.sync.aligned.m16n8k8.row.col.f32.tf32.tf32.f32 "
        "{%0,%1,%2,%3}, {%4,%5,%6,%7}, {%8,%9}, {%0,%1,%2,%3};"
        : "+f"(d[0]), "+f"(d[1]), "+f"(d[2]), "+f"(d[3])
        : "r"(__float_as_uint(a.x)), "r"(__float_as_uint(a.y)),
          "r"(__float_as_uint(a.z)), "r"(__float_as_uint(a.w)),
          "r"(__float_as_uint(b.x)), "r"(__float_as_uint(b.y)));
}

// ============================================================================
// weight transpose: in[R][C] -> out[C][R]
// ============================================================================
__global__ void transpose_kernel(const float* __restrict__ in, float* __restrict__ out,
                                 int R, int C)
{
    __shared__ float t[32][33];
    int c0 = blockIdx.x * 32, r0 = blockIdx.y * 32;
    int x = threadIdx.x, y = threadIdx.y;
#pragma unroll
    for (int i = 0; i < 32; i += 8)
        t[y + i][x] = in[(size_t)(r0 + y + i) * C + c0 + x];
    __syncthreads();
#pragma unroll
    for (int i = 0; i < 32; i += 8)
        out[(size_t)(c0 + y + i) * R + r0 + x] = t[x][y + i];
}

// ============================================================================
// tf32 mma.sync GEMM: C[M,N] = A[M,K] @ Bt[N,K]^T (+bias)
// CTA tile 128x128, warp grid 2(M)x4(N), warp tile 64x32, KC=32, dbl-buffered.
// Smem holds tiles pre-permuted into m16n8k8 fragment order:
//   A: [mt(8)][ks(4)][lane(32)][reg(4)]  (float4/lane per (mt,ks))
//   B: [nt(16)][ks(4)][lane(32)][reg(2)] (float2/lane per (nt,ks))
// MODE 0: row-major out.  MODE 1: scatter into [B][H][L][D].
// ============================================================================
#define KC 32
#define A_FLOATS 4096   // 8*4*32*4
#define B_FLOATS 4096   // 16*4*32*2
#define GEMM_SMEM ((2*A_FLOATS + 2*B_FLOATS) * (int)sizeof(float))

__device__ __forceinline__ void load_tileA(float* __restrict__ dst,
                                           const float* __restrict__ src,
                                           int row0, int ld, int k0, int tid)
{
#pragma unroll
    for (int u = 0; u < 4; u++) {
        int idx = tid + u * 256;
        int r = idx >> 3, c4 = idx & 7;
        float4 v = *(const float4*)(src + (size_t)(row0 + r) * ld + k0 + c4 * 4);
        uint32_t w[4] = {f2tf32(v.x), f2tf32(v.y), f2tf32(v.z), f2tf32(v.w)};
        int mt = r >> 4, r16 = r & 15;
        int lanebase = (r16 & 7) * 4;
        int regbase  = (r16 >> 3);
#pragma unroll
        for (int e = 0; e < 4; e++) {
            int k = c4 * 4 + e;
            int ks = k >> 3, kc = k & 7;
            int lane = lanebase + (kc & 3);
            int reg  = ((kc >> 2) << 1) + regbase;
            dst[(((mt << 2) + ks) << 7) + (lane << 2) + reg] = __uint_as_float(w[e]);
        }
    }
}

__device__ __forceinline__ void load_tileB(float* __restrict__ dst,
                                           const float* __restrict__ src,
                                           int n0, int ld, int k0, int tid)
{
#pragma unroll
    for (int u = 0; u < 4; u++) {
        int idx = tid + u * 256;
        int r = idx >> 3, c4 = idx & 7;   // r = n row of Bt
        float4 v = *(const float4*)(src + (size_t)(n0 + r) * ld + k0 + c4 * 4);
        uint32_t w[4] = {f2tf32(v.x), f2tf32(v.y), f2tf32(v.z), f2tf32(v.w)};
        int nt = r >> 3, n8 = r & 7;
        int lanebase = n8 * 4;
#pragma unroll
        for (int e = 0; e < 4; e++) {
            int k = c4 * 4 + e;
            int ks = k >> 3, kc = k & 7;
            int lane = lanebase + (kc & 3);
            int reg  = kc >> 2;
            dst[(((nt << 2) + ks) << 6) + (lane << 1) + reg] = __uint_as_float(w[e]);
        }
    }
}

template<int MODE, int H>
__global__ void __launch_bounds__(256, 2)
mma_gemm(const float* __restrict__ A, const float* __restrict__ Bt,
         const float* __restrict__ bias, float* __restrict__ C,
         int N, int K)
{
    extern __shared__ float sm[];
    float* As = sm;                    // [2][A_FLOATS]
    float* Bs = sm + 2 * A_FLOATS;     // [2][B_FLOATS]

    const int tid  = threadIdx.x;
    const int wid  = tid >> 5;
    const int lane = tid & 31;
    const int mw   = wid & 1;          // 0/1 -> M half
    const int nw   = wid >> 1;         // 0..3 -> N quarter
    const int m0 = blockIdx.y * 128, n0 = blockIdx.x * 128;

    float acc[4][4][4];
#pragma unroll
    for (int i = 0; i < 4; i++)
#pragma unroll
        for (int j = 0; j < 4; j++)
#pragma unroll
            for (int e = 0; e < 4; e++) acc[i][j][e] = 0.f;

    // prologue: chunk 0 -> buf 0
    load_tileA(As, A,  m0, K, 0, tid);
    load_tileB(Bs, Bt, n0, K, 0, tid);
    __syncthreads();

    const int NT = K / KC;
    for (int kt = 0; kt < NT; kt++) {
        const int buf = kt & 1;
        if (kt + 1 < NT) {
            load_tileA(As + (buf ^ 1) * A_FLOATS, A,  m0, K, (kt + 1) * KC, tid);
            load_tileB(Bs + (buf ^ 1) * B_FLOATS, Bt, n0, K, (kt + 1) * KC, tid);
        }
        const float* ab = As + buf * A_FLOATS;
        const float* bb = Bs + buf * B_FLOATS;
#pragma unroll
        for (int ks = 0; ks < 4; ks++) {
            float4 af[4];
            float2 bf[4];
#pragma unroll
            for (int i = 0; i < 4; i++)
                af[i] = *(const float4*)&ab[((((mw * 4 + i) << 2) + ks) << 7) + (lane << 2)];
#pragma unroll
            for (int j = 0; j < 4; j++)
                bf[j] = *(const float2*)&bb[((((nw * 4 + j) << 2) + ks) << 6) + (lane << 1)];
#pragma unroll
            for (int i = 0; i < 4; i++)
#pragma unroll
                for (int j = 0; j < 4; j++)
                    mma_tf32(acc[i][j], af[i], bf[j]);
        }
        __syncthreads();
    }

    // epilogue: c0,c1 at (row, col), c2,c3 at (row+8, col); col = even
    const int rbase = m0 + mw * 64 + (lane >> 2);
    const int cbase = n0 + nw * 32 + (lane & 3) * 2;
#pragma unroll
    for (int i = 0; i < 4; i++) {
#pragma unroll
        for (int j = 0; j < 4; j++) {
            int col = cbase + j * 8;
            float2 lo, hi;
            lo.x = acc[i][j][0]; lo.y = acc[i][j][1];
            hi.x = acc[i][j][2]; hi.y = acc[i][j][3];
            if (bias) {
                float bx = bias[col], by = bias[col + 1];
                lo.x += bx; lo.y += by;
                hi.x += bx; hi.y += by;
            }
            int row = rbase + i * 16;
            if (MODE == 0) {
                *(float2*)&C[(size_t)row * N + col]       = lo;
                *(float2*)&C[(size_t)(row + 8) * N + col] = hi;
            } else {
                int h = col >> 7, d = col & 127;
                int b  = row >> 11, l  = row & 2047;
                int b2 = (row + 8) >> 11, l2 = (row + 8) & 2047;
                *(float2*)&C[(((size_t)(b  * H + h)) * L_ + l ) * D_ + d] = lo;
                *(float2*)&C[(((size_t)(b2 * H + h)) * L_ + l2) * D_ + d] = hi;
            }
        }
    }
}

// ============================================================================
// RoPE (unchanged)
// ============================================================================
__global__ void rope_kernel(float* __restrict__ x, int total)
{
    int idx = blockIdx.x * blockDim.x + threadIdx.x;
    if (idx >= total) return;
    int d  = idx & 63;
    int l  = (idx >> 6) & (L_ - 1);
    int bh = idx >> 17;
    size_t base = ((size_t)bh * L_ + l) * D_;
    float inv = powf(1.0e6f, -(float)d * (1.0f / 64.0f));
    float ang = (float)l * inv;
    float s, c;
    sincosf(ang, &s, &c);
    float x1 = x[base + d], x2 = x[base + d + 64];
    x[base + d]      = x1 * c - x2 * s;
    x[base + d + 64] = x2 * c + x1 * s;
}

// ============================================================================
// Causal flash attention, fp32 (unchanged from passing round)
// ============================================================================
#define FLASH_SMEM ((128 * PAD * 2 + 64 * 128 + 64 * PAD) * (int)sizeof(float))

__global__ void __launch_bounds__(256) flash_kernel(
    const float* __restrict__ q, const float* __restrict__ k,
    const float* __restrict__ v, float* __restrict__ out)
{
    extern __shared__ float sm[];
    float* Qs = sm;
    float* Ks = Qs + 128 * PAD;
    float* Vs = Ks + 128 * PAD;
    float* Ps = Vs + 64 * 128;

    const int tid = threadIdx.x;
    const int tx = tid & 15, ty = tid >> 4;
    const int qt = blockIdx.x, h = blockIdx.y, b = blockIdx.z;
    const int hk = h / G_;
    const float scale = 0.08838834764831845f;

    const float* qp = q + (((size_t)b * HQ_ + h) * L_ + (size_t)qt * BM) * D_;
    const float* kp = k + ((size_t)b * HKV_ + hk) * L_ * D_;
    const float* vp = v + ((size_t)b * HKV_ + hk) * L_ * D_;

#pragma unroll
    for (int u = 0; u < 8; u++) {
        int f4 = tid + u * 256;
        int r = f4 >> 5, c4 = f4 & 31;
        float4 val = *(const float4*)&qp[(size_t)r * 128 + c4 * 4];
        Qs[(c4 * 4 + 0) * PAD + r] = val.x;
        Qs[(c4 * 4 + 1) * PAD + r] = val.y;
        Qs[(c4 * 4 + 2) * PAD + r] = val.z;
        Qs[(c4 * 4 + 3) * PAD + r] = val.w;
    }

    float m[4], lsum[4], o[4][8];
#pragma unroll
    for (int i = 0; i < 4; i++) {
        m[i] = -1e30f; lsum[i] = 0.f;
#pragma unroll
        for (int j = 0; j < 8; j++) o[i][j] = 0.f;
    }

    for (int kt = 0; kt <= qt; kt++) {
        const float* kpt = kp + (size_t)kt * BN * D_;
        const float* vpt = vp + (size_t)kt * BN * D_;
#pragma unroll
        for (int u = 0; u < 8; u++) {
            int f4 = tid + u * 256;
            int r = f4 >> 5, c4 = f4 & 31;
            float4 kv4 = *(const float4*)&kpt[(size_t)r * 128 + c4 * 4];
            Ks[(c4 * 4 + 0) * PAD + r] = kv4.x;
            Ks[(c4 * 4 + 1) * PAD + r] = kv4.y;
            Ks[(c4 * 4 + 2) * PAD + r] = kv4.z;
            Ks[(c4 * 4 + 3) * PAD + r] = kv4.w;
            float4 vv4 = *(const float4*)&vpt[(size_t)r * 128 + c4 * 4];
            *(float4*)&Vs[r * 128 + c4 * 4] = vv4;
        }
        __syncthreads();

        float s[4][4];
#pragma unroll
        for (int i = 0; i < 4; i++)
#pragma unroll
            for (int j = 0; j < 4; j++) s[i][j] = 0.f;

#pragma unroll 4
        for (int kk = 0; kk < 128; kk++) {
            float4 qv = *(const float4*)&Qs[kk * PAD + ty * 4];
            float4 kv = *(const float4*)&Ks[kk * PAD + tx * 4];
            float qa[4] = {qv.x, qv.y, qv.z, qv.w};
            float ka[4] = {kv.x, kv.y, kv.z, kv.w};
#pragma unroll
            for (int i = 0; i < 4; i++)
#pragma unroll
                for (int j = 0; j < 4; j++)
                    s[i][j] = fmaf(qa[i], ka[j], s[i][j]);
        }

#pragma unroll
        for (int i = 0; i < 4; i++)
#pragma unroll
            for (int j = 0; j < 4; j++) {
                s[i][j] *= scale;
                if (kt == qt && (tx * 4 + j) > (ty * 4 + i)) s[i][j] = -1e30f;
            }

#pragma unroll
        for (int i = 0; i < 4; i++) {
            float rm = fmaxf(fmaxf(s[i][0], s[i][1]), fmaxf(s[i][2], s[i][3]));
#pragma unroll
            for (int off = 8; off >= 1; off >>= 1)
                rm = fmaxf(rm, __shfl_xor_sync(0xffffffffu, rm, off, 16));
            float mn = fmaxf(m[i], rm);
            float alpha = __expf(m[i] - mn);
            float p0 = __expf(s[i][0] - mn);
            float p1 = __expf(s[i][1] - mn);
            float p2 = __expf(s[i][2] - mn);
            float p3 = __expf(s[i][3] - mn);
            float rs = p0 + p1 + p2 + p3;
#pragma unroll
            for (int off = 8; off >= 1; off >>= 1)
                rs += __shfl_xor_sync(0xffffffffu, rs, off, 16);
            lsum[i] = lsum[i] * alpha + rs;
            m[i] = mn;
#pragma unroll
            for (int j = 0; j < 8; j++) o[i][j] *= alpha;
            Ps[(ty * 4 + i) * PAD + tx * 4 + 0] = p0;
            Ps[(ty * 4 + i) * PAD + tx * 4 + 1] = p1;
            Ps[(ty * 4 + i) * PAD + tx * 4 + 2] = p2;
            Ps[(ty * 4 + i) * PAD + tx * 4 + 3] = p3;
        }
        __syncthreads();

#pragma unroll 2
        for (int c = 0; c < BN; c++) {
            float4 v0 = *(const float4*)&Vs[c * 128 + tx * 4];
            float4 v1 = *(const float4*)&Vs[c * 128 + 64 + tx * 4];
#pragma unroll
            for (int i = 0; i < 4; i++) {
                float pi = Ps[(ty * 4 + i) * PAD + c];
                o[i][0] = fmaf(pi, v0.x, o[i][0]);
                o[i][1] = fmaf(pi, v0.y, o[i][1]);
                o[i][2] = fmaf(pi, v0.z, o[i][2]);
                o[i][3] = fmaf(pi, v0.w, o[i][3]);
                o[i][4] = fmaf(pi, v1.x, o[i][4]);
                o[i][5] = fmaf(pi, v1.y, o[i][5]);
                o[i][6] = fmaf(pi, v1.z, o[i][6]);
                o[i][7] = fmaf(pi, v1.w, o[i][7]);
            }
        }
        __syncthreads();
    }

#pragma unroll
    for (int i = 0; i < 4; i++) {
        float inv = 1.0f / lsum[i];
        int qrow = qt * BM + ty * 4 + i;
        float* op = out + ((size_t)b * L_ + qrow) * (HQ_ * D_) + h * D_;
        float4 r0, r1;
        r0.x = o[i][0] * inv; r0.y = o[i][1] * inv;
        r0.z = o[i][2] * inv; r0.w = o[i][3] * inv;
        r1.x = o[i][4] * inv; r1.y = o[i][5] * inv;
        r1.z = o[i][6] * inv; r1.w = o[i][7] * inv;
        *(float4*)&op[tx * 4]      = r0;
        *(float4*)&op[64 + tx * 4] = r1;
    }
}

// ============================================================================
// launch
// ============================================================================
extern "C" void kernel_launch(void* const* d_in, const int* in_sizes, int n_in,
                              void* d_out, int out_size)
{
    (void)in_sizes; (void)n_in; (void)out_size;
    const float* hs = (const float*)d_in[0];
    const float* Wq = (const float*)d_in[1];
    const float* bq = (const float*)d_in[2];
    const float* Wk = (const float*)d_in[3];
    const float* bk = (const float*)d_in[4];
    const float* Wv = (const float*)d_in[5];
    const float* bv = (const float*)d_in[6];
    const float* Wo = (const float*)d_in[7];
    float* out = (float*)d_out;

    float *qg, *kg, *vg, *ctx, *wtq, *wtk, *wtv, *wto;
    cudaGetSymbolAddress((void**)&qg,  g_q);
    cudaGetSymbolAddress((void**)&kg,  g_k);
    cudaGetSymbolAddress((void**)&vg,  g_v);
    cudaGetSymbolAddress((void**)&ctx, g_ctx);
    cudaGetSymbolAddress((void**)&wtq, g_wtq);
    cudaGetSymbolAddress((void**)&wtk, g_wtk);
    cudaGetSymbolAddress((void**)&wtv, g_wtv);
    cudaGetSymbolAddress((void**)&wto, g_wto);

    cudaFuncSetAttribute(flash_kernel,
                         cudaFuncAttributeMaxDynamicSharedMemorySize, FLASH_SMEM);
    cudaFuncSetAttribute(mma_gemm<0, 1>,
                         cudaFuncAttributeMaxDynamicSharedMemorySize, GEMM_SMEM);
    cudaFuncSetAttribute(mma_gemm<1, HQ_>,
                         cudaFuncAttributeMaxDynamicSharedMemorySize, GEMM_SMEM);
    cudaFuncSetAttribute(mma_gemm<1, HKV_>,
                         cudaFuncAttributeMaxDynamicSharedMemorySize, GEMM_SMEM);

    dim3 tb(32, 8);
    // weight transposes: W[K][N] -> Wt[N][K]
    transpose_kernel<<<dim3((HQ_*D_)/32,  E_/32), tb>>>(Wq, wtq, E_, HQ_*D_);
    transpose_kernel<<<dim3((HKV_*D_)/32, E_/32), tb>>>(Wk, wtk, E_, HKV_*D_);
    transpose_kernel<<<dim3((HKV_*D_)/32, E_/32), tb>>>(Wv, wtv, E_, HKV_*D_);
    transpose_kernel<<<dim3(E_/32,        E_/32), tb>>>(Wo, wto, E_, E_);

    // projections (tf32 mma.sync)
    mma_gemm<1, HQ_ ><<<dim3((HQ_*D_)/128,  M_/128), 256, GEMM_SMEM>>>(hs, wtq, bq, qg, HQ_*D_,  E_);
    mma_gemm<1, HKV_><<<dim3((HKV_*D_)/128, M_/128), 256, GEMM_SMEM>>>(hs, wtk, bk, kg, HKV_*D_, E_);
    mma_gemm<1, HKV_><<<dim3((HKV_*D_)/128, M_/128), 256, GEMM_SMEM>>>(hs, wtv, bv, vg, HKV_*D_, E_);

    // RoPE
    const int tq = B_ * HQ_ * L_ * 64;
    const int tk = B_ * HKV_ * L_ * 64;
    rope_kernel<<<(tq + 255) / 256, 256>>>(qg, tq);
    rope_kernel<<<(tk + 255) / 256, 256>>>(kg, tk);

    // attention (fp32 flash)
    flash_kernel<<<dim3(L_ / BM, HQ_, B_), 256, FLASH_SMEM>>>(qg, kg, vg, ctx);

    // output projection
    mma_gemm<0, 1><<<dim3(E_/128, M_/128), 256, GEMM_SMEM>>>(ctx, wto, nullptr, out, E_, E_);
}